// round 8
// baseline (speedup 1.0000x reference)
#include <cuda_runtime.h>
#include <math.h>

// Problem constants
#define BB 2
#define LL 2048
#define DD 1024
#define NS 16        // D_STATE
#define RK 64        // DT_RANK
#define NE 96        // RK + 2*NS
#define NROW (BB*LL) // 4096
#define NC 64        // chunks per sequence
#define LC (LL/NC)   // 32 steps per chunk
#define DDNS (DD*NS) // 16384

typedef unsigned long long ull;

// Scratch (device globals; no allocations allowed)
__device__ float g_xp0[NROW * NE];       // K-split partial 0
__device__ float g_xp1[NROW * NE];       // K-split partial 1
__device__ float g_delta[NROW * DD];     // [row][d]
__device__ float g_sdl[BB * NC * DD];    // per-chunk sum of delta
__device__ float g_ho[BB * NC * DDNS];
__device__ float g_hi[BB * NC * DDNS];

__device__ __forceinline__ float ex2f_fast(float x) {
    float r;
    asm("ex2.approx.f32 %0, %1;" : "=f"(r) : "f"(x));
    return r;
}
__device__ __forceinline__ float lg2f_fast(float x) {
    float r;
    asm("lg2.approx.f32 %0, %1;" : "=f"(r) : "f"(x));
    return r;
}
// packed fp32 helpers (Blackwell f32x2 pipe)
__device__ __forceinline__ ull f2p(float lo, float hi) {
    ull r;
    asm("mov.b64 %0, {%1, %2};" : "=l"(r) : "f"(lo), "f"(hi));
    return r;
}
__device__ __forceinline__ void p2f(ull p, float& lo, float& hi) {
    asm("mov.b64 {%0, %1}, %2;" : "=f"(lo), "=f"(hi) : "l"(p));
}
__device__ __forceinline__ ull fma2p(ull a, ull b, ull c) {
    ull d;
    asm("fma.rn.f32x2 %0, %1, %2, %3;" : "=l"(d) : "l"(a), "l"(b), "l"(c));
    return d;
}
__device__ __forceinline__ ull mul2p(ull a, ull b) {
    ull d;
    asm("mul.rn.f32x2 %0, %1, %2;" : "=l"(d) : "l"(a), "l"(b));
    return d;
}

// Packed polynomial exp2 on the FMA/ALU pipes (MUFU offload).
// Valid for x <= 0 (args are dl*A2 <= 0). Degree-5 Taylor on [-0.5, 0.5]
// after round-to-nearest reduction: rel err ~2.4e-6.
__device__ __forceinline__ ull exp2p_poly(float x0, float x1) {
    x0 = fmaxf(x0, -125.0f);
    x1 = fmaxf(x1, -125.0f);
    int i0 = __float2int_rn(x0);
    int i1 = __float2int_rn(x1);
    float r0 = x0 - (float)i0;
    float r1 = x1 - (float)i1;
    float s0 = __int_as_float((i0 << 23) + 0x3f800000);
    float s1 = __int_as_float((i1 << 23) + 0x3f800000);
    ull r = f2p(r0, r1);
    ull p = fma2p(r, f2p(1.3333558e-3f, 1.3333558e-3f), f2p(9.6181291e-3f, 9.6181291e-3f));
    p = fma2p(r, p, f2p(5.5504109e-2f, 5.5504109e-2f));
    p = fma2p(r, p, f2p(2.4022651e-1f, 2.4022651e-1f));
    p = fma2p(r, p, f2p(6.9314718e-1f, 6.9314718e-1f));
    p = fma2p(r, p, f2p(1.0f, 1.0f));
    return mul2p(p, f2p(s0, s1));
}

// ---------------------------------------------------------------------------
// GEMM1: xp[row, e] = sum_k x[row, k] * Wx[e, k]    (M=4096, N=96, K=1024)
// K-split 2. Tile 64 rows x 96 cols, BK=32, 256 threads, micro 8x3.
// b stored PRE-DUPLICATED as f32x2 pairs in smem (no f2p in inner loop).
// ---------------------------------------------------------------------------
__global__ void __launch_bounds__(256) k_gemm1(const float* __restrict__ x,
                                               const float* __restrict__ wx) {
    __shared__ float xs_t[32][68];   // [k][row]
    __shared__ ull   wsp[32][100];   // [k][col] as (b,b) pairs

    const int t = threadIdx.x;
    const int row0 = blockIdx.x * 64;
    const int kbase = blockIdx.y * 512;
    const int trow8 = (t >> 5) * 8;
    const int tcol = t & 31;

    const int xr0 = t >> 3;
    const int xr1 = 32 + (t >> 3);
    const int xk = (t & 7) << 2;

    float4 xa0, xa1;
    float4 wa[3];
    xa0 = *(const float4*)(x + (size_t)(row0 + xr0) * DD + kbase + xk);
    xa1 = *(const float4*)(x + (size_t)(row0 + xr1) * DD + kbase + xk);
    #pragma unroll
    for (int q = 0; q < 3; ++q) {
        int idx = t + q * 256;
        int r = idx >> 3;
        int kk = (idx & 7) << 2;
        wa[q] = *(const float4*)(wx + (size_t)r * DD + kbase + kk);
    }

    ull acc2[4][3] = {};

    for (int k0 = 0; k0 < 512; k0 += 32) {
        xs_t[xk + 0][xr0] = xa0.x;
        xs_t[xk + 1][xr0] = xa0.y;
        xs_t[xk + 2][xr0] = xa0.z;
        xs_t[xk + 3][xr0] = xa0.w;
        xs_t[xk + 0][xr1] = xa1.x;
        xs_t[xk + 1][xr1] = xa1.y;
        xs_t[xk + 2][xr1] = xa1.z;
        xs_t[xk + 3][xr1] = xa1.w;
        #pragma unroll
        for (int q = 0; q < 3; ++q) {
            int idx = t + q * 256;
            int r = idx >> 3;
            int kk = (idx & 7) << 2;
            wsp[kk + 0][r] = f2p(wa[q].x, wa[q].x);
            wsp[kk + 1][r] = f2p(wa[q].y, wa[q].y);
            wsp[kk + 2][r] = f2p(wa[q].z, wa[q].z);
            wsp[kk + 3][r] = f2p(wa[q].w, wa[q].w);
        }
        __syncthreads();

        if (k0 + 32 < 512) {
            xa0 = *(const float4*)(x + (size_t)(row0 + xr0) * DD + kbase + (k0 + 32) + xk);
            xa1 = *(const float4*)(x + (size_t)(row0 + xr1) * DD + kbase + (k0 + 32) + xk);
            #pragma unroll
            for (int q = 0; q < 3; ++q) {
                int idx = t + q * 256;
                int r = idx >> 3;
                int kk = (idx & 7) << 2;
                wa[q] = *(const float4*)(wx + (size_t)r * DD + kbase + (k0 + 32) + kk);
            }
        }

        #pragma unroll
        for (int kk = 0; kk < 32; ++kk) {
            ulonglong2 A0 = *(const ulonglong2*)&xs_t[kk][trow8];
            ulonglong2 A1 = *(const ulonglong2*)&xs_t[kk][trow8 + 4];
            ull b0p = wsp[kk][tcol];
            ull b1p = wsp[kk][tcol + 32];
            ull b2p = wsp[kk][tcol + 64];
            acc2[0][0] = fma2p(A0.x, b0p, acc2[0][0]);
            acc2[0][1] = fma2p(A0.x, b1p, acc2[0][1]);
            acc2[0][2] = fma2p(A0.x, b2p, acc2[0][2]);
            acc2[1][0] = fma2p(A0.y, b0p, acc2[1][0]);
            acc2[1][1] = fma2p(A0.y, b1p, acc2[1][1]);
            acc2[1][2] = fma2p(A0.y, b2p, acc2[1][2]);
            acc2[2][0] = fma2p(A1.x, b0p, acc2[2][0]);
            acc2[2][1] = fma2p(A1.x, b1p, acc2[2][1]);
            acc2[2][2] = fma2p(A1.x, b2p, acc2[2][2]);
            acc2[3][0] = fma2p(A1.y, b0p, acc2[3][0]);
            acc2[3][1] = fma2p(A1.y, b1p, acc2[3][1]);
            acc2[3][2] = fma2p(A1.y, b2p, acc2[3][2]);
        }
        __syncthreads();
    }

    float* dst = blockIdx.y ? g_xp1 : g_xp0;
    #pragma unroll
    for (int p = 0; p < 4; ++p) {
        #pragma unroll
        for (int j = 0; j < 3; ++j) {
            float lo, hi;
            p2f(acc2[p][j], lo, hi);
            dst[(size_t)(row0 + trow8 + 2 * p) * NE + tcol + 32 * j] = lo;
            dst[(size_t)(row0 + trow8 + 2 * p + 1) * NE + tcol + 32 * j] = hi;
        }
    }
}

// ---------------------------------------------------------------------------
// GEMM2: delta[row, d] = softplus( sum_r dr[row, r] * Wdt[d, r] + bias[d] )
// ---------------------------------------------------------------------------
__global__ void __launch_bounds__(256) k_gemm2(const float* __restrict__ wdt,
                                               const float* __restrict__ bias) {
    __shared__ float ds_t[64][66];   // [k][row]
    __shared__ float ws2[64][64];    // [k][col]
    const int t = threadIdx.x;
    const int row0 = blockIdx.y * 64;
    const int col0 = blockIdx.x * 64;

    #pragma unroll
    for (int q = 0; q < 4; ++q) {
        int idx = t + q * 256;
        int r = idx >> 4;
        int kk = (idx & 15) << 2;
        float4 v0 = *(const float4*)(g_xp0 + (size_t)(row0 + r) * NE + kk);
        float4 v1 = *(const float4*)(g_xp1 + (size_t)(row0 + r) * NE + kk);
        ds_t[kk + 0][r] = v0.x + v1.x;
        ds_t[kk + 1][r] = v0.y + v1.y;
        ds_t[kk + 2][r] = v0.z + v1.z;
        ds_t[kk + 3][r] = v0.w + v1.w;
    }
    #pragma unroll
    for (int q = 0; q < 4; ++q) {
        int idx = t + q * 256;
        int r = idx >> 4;
        int kk = (idx & 15) << 2;
        float4 v = *(const float4*)(wdt + (size_t)(col0 + r) * RK + kk);
        ws2[kk][r] = v.x; ws2[kk + 1][r] = v.y; ws2[kk + 2][r] = v.z; ws2[kk + 3][r] = v.w;
    }
    __syncthreads();

    const int trow8 = (t >> 5) * 8;
    const int tcol = t & 31;

    ull acc2[4][2] = {};
    #pragma unroll
    for (int kk = 0; kk < 64; ++kk) {
        float b0 = ws2[kk][tcol];
        float b1 = ws2[kk][tcol + 32];
        ull b0p = f2p(b0, b0);
        ull b1p = f2p(b1, b1);
        #pragma unroll
        for (int p = 0; p < 4; ++p) {
            ull a = *(const ull*)&ds_t[kk][trow8 + 2 * p];
            acc2[p][0] = fma2p(a, b0p, acc2[p][0]);
            acc2[p][1] = fma2p(a, b1p, acc2[p][1]);
        }
    }

    #pragma unroll
    for (int p = 0; p < 4; ++p) {
        #pragma unroll
        for (int j = 0; j < 2; ++j) {
            float lo, hi;
            p2f(acc2[p][j], lo, hi);
            int col = col0 + tcol + 32 * j;
            float bcol = bias[col];
            #pragma unroll
            for (int hh = 0; hh < 2; ++hh) {
                int row = row0 + trow8 + 2 * p + hh;
                float z = (hh == 0 ? lo : hi) + bcol;
                float az = fabsf(z);
                float e = ex2f_fast(-1.4426950408889634f * az);
                float l = lg2f_fast(1.0f + e) * 0.69314718055994531f;
                g_delta[(size_t)row * DD + col] = fmaxf(z, 0.0f) + l;
            }
        }
    }
}

// ---------------------------------------------------------------------------
// Scan pass 1: per (b, d, chunk) thread; B staged in smem; writes h_out + sdl.
// Pairs q=0..5 on MUFU, q=6,7 on FMA-pipe polynomial (pipe balancing).
// ---------------------------------------------------------------------------
__global__ void __launch_bounds__(128) k_scan1(const float* __restrict__ x,
                                               const float* __restrict__ A_log) {
    __shared__ float s_b[LC][16];
    const int t = threadIdx.x;
    const int d = blockIdx.x * 128 + t;
    const int c = blockIdx.y;
    const int b = blockIdx.z;
    const int rbase = b * LL + c * LC;

    {
        int row = t >> 2;
        int c4 = (t & 3) << 2;
        float4 v0 = *(const float4*)(g_xp0 + (size_t)(rbase + row) * NE + RK + c4);
        float4 v1 = *(const float4*)(g_xp1 + (size_t)(rbase + row) * NE + RK + c4);
        float4 s; s.x = v0.x + v1.x; s.y = v0.y + v1.y; s.z = v0.z + v1.z; s.w = v0.w + v1.w;
        *(float4*)&s_b[row][c4] = s;
    }

    const float l2e = 1.4426950408889634f;
    float A2[NS];
    #pragma unroll
    for (int q = 0; q < 4; ++q) {
        float4 v = *(const float4*)(A_log + (size_t)d * NS + q * 4);
        A2[q * 4 + 0] = -__expf(v.x) * l2e;
        A2[q * 4 + 1] = -__expf(v.y) * l2e;
        A2[q * 4 + 2] = -__expf(v.z) * l2e;
        A2[q * 4 + 3] = -__expf(v.w) * l2e;
    }
    __syncthreads();

    ull h2[8] = {};
    float sdl = 0.0f;

    const float* dptr = g_delta + (size_t)rbase * DD + d;
    const float* xptr = x + (size_t)rbase * DD + d;
    float dl = dptr[0];
    float xv = xptr[0];

    #pragma unroll 4
    for (int s = 0; s < LC; ++s) {
        float dln = 0.f, xvn = 0.f;
        if (s + 1 < LC) {
            dln = dptr[(size_t)(s + 1) * DD];
            xvn = xptr[(size_t)(s + 1) * DD];
        }
        sdl += dl;
        const float dx = dl * xv;
        const ull dxp = f2p(dx, dx);
        ulonglong2 Bq[4];
        #pragma unroll
        for (int u = 0; u < 4; ++u)
            Bq[u] = *(const ulonglong2*)&s_b[s][4 * u];
        #pragma unroll
        for (int q = 0; q < 8; ++q) {
            ull a2;
            if (q < 6) {
                float e0 = ex2f_fast(dl * A2[2 * q]);
                float e1 = ex2f_fast(dl * A2[2 * q + 1]);
                a2 = f2p(e0, e1);
            } else {
                a2 = exp2p_poly(dl * A2[2 * q], dl * A2[2 * q + 1]);
            }
            ull Bv = (q & 1) ? Bq[q >> 1].y : Bq[q >> 1].x;
            h2[q] = fma2p(a2, h2[q], mul2p(dxp, Bv));
        }
        dl = dln; xv = xvn;
    }

    const size_t off = ((size_t)(b * NC + c) * DD + d) * NS;
    #pragma unroll
    for (int u = 0; u < 4; ++u) {
        ulonglong2 st;
        st.x = h2[2 * u]; st.y = h2[2 * u + 1];
        *(ulonglong2*)(g_ho + off + u * 4) = st;
    }
    g_sdl[(size_t)(b * NC + c) * DD + d] = sdl;
}

// ---------------------------------------------------------------------------
// Combine: per (b,d,n) thread over 64 chunks; ap recomputed from sdl on the fly.
// ---------------------------------------------------------------------------
__global__ void __launch_bounds__(128) k_comb(const float* __restrict__ A_log) {
    const int gid = blockIdx.x * 128 + threadIdx.x;     // 0 .. BB*DDNS-1
    const int b = gid >> 14;            // DDNS = 16384
    const int rem = gid & (DDNS - 1);   // d*NS + n
    const int d = rem >> 4;
    const int n = rem & 15;

    const float A2 = -__expf(A_log[(size_t)d * NS + n]) * 1.4426950408889634f;

    float h = 0.0f;
    #pragma unroll
    for (int c0 = 0; c0 < NC; c0 += 16) {
        float sv[16], hv[16];
        #pragma unroll
        for (int j = 0; j < 16; ++j) {
            const int c = c0 + j;
            sv[j] = g_sdl[(size_t)(b * NC + c) * DD + d];
            hv[j] = g_ho[(size_t)(b * NC + c) * DDNS + rem];
        }
        #pragma unroll
        for (int j = 0; j < 16; ++j) {
            const size_t off = (size_t)(b * NC + c0 + j) * DDNS + rem;
            g_hi[off] = h;
            h = fmaf(ex2f_fast(A2 * sv[j]), h, hv[j]);
        }
    }
}

// ---------------------------------------------------------------------------
// Scan pass 2: replay with h_in; B and C staged in smem; y output.
// Pairs q=0..5 on MUFU, q=6,7 on FMA-pipe polynomial.
// ---------------------------------------------------------------------------
__global__ void __launch_bounds__(128) k_scan2(const float* __restrict__ x,
                                               const float* __restrict__ A_log,
                                               const float* __restrict__ Dw,
                                               float* __restrict__ out) {
    __shared__ float s_bc[LC][32];   // [step][0..15 = B, 16..31 = C]
    const int t = threadIdx.x;
    const int d = blockIdx.x * 128 + t;
    const int c = blockIdx.y;
    const int b = blockIdx.z;
    const int rbase = b * LL + c * LC;

    {
        int row = t >> 2;
        int c4 = (t & 3) << 2;
        float4 v0 = *(const float4*)(g_xp0 + (size_t)(rbase + row) * NE + RK + c4);
        float4 v1 = *(const float4*)(g_xp1 + (size_t)(rbase + row) * NE + RK + c4);
        float4 s0; s0.x = v0.x + v1.x; s0.y = v0.y + v1.y; s0.z = v0.z + v1.z; s0.w = v0.w + v1.w;
        *(float4*)&s_bc[row][c4] = s0;
        float4 w0 = *(const float4*)(g_xp0 + (size_t)(rbase + row) * NE + RK + NS + c4);
        float4 w1 = *(const float4*)(g_xp1 + (size_t)(rbase + row) * NE + RK + NS + c4);
        float4 s1; s1.x = w0.x + w1.x; s1.y = w0.y + w1.y; s1.z = w0.z + w1.z; s1.w = w0.w + w1.w;
        *(float4*)&s_bc[row][16 + c4] = s1;
    }

    const float l2e = 1.4426950408889634f;
    float A2[NS];
    #pragma unroll
    for (int q = 0; q < 4; ++q) {
        float4 v = *(const float4*)(A_log + (size_t)d * NS + q * 4);
        A2[q * 4 + 0] = -__expf(v.x) * l2e;
        A2[q * 4 + 1] = -__expf(v.y) * l2e;
        A2[q * 4 + 2] = -__expf(v.z) * l2e;
        A2[q * 4 + 3] = -__expf(v.w) * l2e;
    }
    const float Dv = Dw[d];

    ull h2[8];
    {
        const size_t off = ((size_t)(b * NC + c) * DD + d) * NS;
        #pragma unroll
        for (int u = 0; u < 4; ++u) {
            ulonglong2 v = *(const ulonglong2*)(g_hi + off + u * 4);
            h2[2 * u] = v.x;
            h2[2 * u + 1] = v.y;
        }
    }
    __syncthreads();

    const float* dptr = g_delta + (size_t)rbase * DD + d;
    const float* xptr = x + (size_t)rbase * DD + d;
    float dl = dptr[0];
    float xv = xptr[0];

    #pragma unroll 4
    for (int s = 0; s < LC; ++s) {
        float dln = 0.f, xvn = 0.f;
        if (s + 1 < LC) {
            dln = dptr[(size_t)(s + 1) * DD];
            xvn = xptr[(size_t)(s + 1) * DD];
        }
        const float dx = dl * xv;
        const ull dxp = f2p(dx, dx);
        ulonglong2 Bq[4], Cq[4];
        #pragma unroll
        for (int u = 0; u < 4; ++u) {
            Bq[u] = *(const ulonglong2*)&s_bc[s][4 * u];
            Cq[u] = *(const ulonglong2*)&s_bc[s][16 + 4 * u];
        }

        ull y2 = 0;
        #pragma unroll
        for (int q = 0; q < 8; ++q) {
            ull a2;
            if (q < 6) {
                float e0 = ex2f_fast(dl * A2[2 * q]);
                float e1 = ex2f_fast(dl * A2[2 * q + 1]);
                a2 = f2p(e0, e1);
            } else {
                a2 = exp2p_poly(dl * A2[2 * q], dl * A2[2 * q + 1]);
            }
            ull Bv = (q & 1) ? Bq[q >> 1].y : Bq[q >> 1].x;
            ull Cv = (q & 1) ? Cq[q >> 1].y : Cq[q >> 1].x;
            h2[q] = fma2p(a2, h2[q], mul2p(dxp, Bv));
            y2 = fma2p(h2[q], Cv, y2);
        }
        float ylo, yhi;
        p2f(y2, ylo, yhi);
        out[(size_t)(rbase + s) * DD + d] = fmaf(xv, Dv, ylo + yhi);
        dl = dln; xv = xvn;
    }
}

// ---------------------------------------------------------------------------
extern "C" void kernel_launch(void* const* d_in, const int* in_sizes, int n_in,
                              void* d_out, int out_size) {
    const float* x     = (const float*)d_in[0];
    const float* A_log = (const float*)d_in[1];
    const float* Dw    = (const float*)d_in[2];
    const float* wx    = (const float*)d_in[3];
    const float* wdt   = (const float*)d_in[4];
    const float* bias  = (const float*)d_in[5];
    float* out = (float*)d_out;

    dim3 g1(NROW / 64, 2);
    k_gemm1<<<g1, 256>>>(x, wx);

    dim3 g2(DD / 64, NROW / 64);
    k_gemm2<<<g2, 256>>>(wdt, bias);

    dim3 gs(DD / 128, NC, BB);
    k_scan1<<<gs, 128>>>(x, A_log);

    k_comb<<<(BB * DDNS) / 128, 128>>>(A_log);

    k_scan2<<<gs, 128>>>(x, A_log, Dw, out);
}

// round 9
// speedup vs baseline: 1.1820x; 1.1820x over previous
#include <cuda_runtime.h>
#include <math.h>

// Problem constants
#define BB 2
#define LL 2048
#define DD 1024
#define NS 16        // D_STATE
#define RK 64        // DT_RANK
#define NE 96        // RK + 2*NS
#define NROW (BB*LL) // 4096
#define NC 64        // chunks per sequence
#define LC (LL/NC)   // 32 steps per chunk
#define DDNS (DD*NS) // 16384

typedef unsigned long long ull;

// Scratch (device globals; no allocations allowed)
__device__ float g_xp0[NROW * NE];       // K-split partial 0
__device__ float g_xp1[NROW * NE];       // K-split partial 1
__device__ float g_delta[NROW * DD];     // [row][d]
__device__ float g_sdl[BB * NC * DD];    // per-chunk sum of delta
__device__ float g_ho[BB * NC * DDNS];
__device__ float g_hi[BB * NC * DDNS];

__device__ __forceinline__ float ex2f_fast(float x) {
    float r;
    asm("ex2.approx.f32 %0, %1;" : "=f"(r) : "f"(x));
    return r;
}
__device__ __forceinline__ float lg2f_fast(float x) {
    float r;
    asm("lg2.approx.f32 %0, %1;" : "=f"(r) : "f"(x));
    return r;
}
// packed fp32 helpers (Blackwell f32x2 pipe)
__device__ __forceinline__ ull f2p(float lo, float hi) {
    ull r;
    asm("mov.b64 %0, {%1, %2};" : "=l"(r) : "f"(lo), "f"(hi));
    return r;
}
__device__ __forceinline__ void p2f(ull p, float& lo, float& hi) {
    asm("mov.b64 {%0, %1}, %2;" : "=f"(lo), "=f"(hi) : "l"(p));
}
__device__ __forceinline__ ull fma2p(ull a, ull b, ull c) {
    ull d;
    asm("fma.rn.f32x2 %0, %1, %2, %3;" : "=l"(d) : "l"(a), "l"(b), "l"(c));
    return d;
}
__device__ __forceinline__ ull mul2p(ull a, ull b) {
    ull d;
    asm("mul.rn.f32x2 %0, %1, %2;" : "=l"(d) : "l"(a), "l"(b));
    return d;
}

// ---------------------------------------------------------------------------
// GEMM1: xp[row, e] = sum_k x[row, k] * Wx[e, k]    (M=4096, N=96, K=1024)
// K-split 2. Tile 64 rows x 96 cols, BK=32, 256 threads, micro 8x3 (4 ull x 3).
// ---------------------------------------------------------------------------
__global__ void __launch_bounds__(256) k_gemm1(const float* __restrict__ x,
                                               const float* __restrict__ wx) {
    __shared__ float xs_t[32][68];   // [k][row]
    __shared__ float ws[32][100];    // [k][col]

    const int t = threadIdx.x;
    const int row0 = blockIdx.x * 64;
    const int kbase = blockIdx.y * 512;
    const int trow8 = (t >> 5) * 8;
    const int tcol = t & 31;

    const int xr0 = t >> 3;
    const int xr1 = 32 + (t >> 3);
    const int xk = (t & 7) << 2;

    float4 xa0, xa1;
    float4 wa[3];
    xa0 = *(const float4*)(x + (size_t)(row0 + xr0) * DD + kbase + xk);
    xa1 = *(const float4*)(x + (size_t)(row0 + xr1) * DD + kbase + xk);
    #pragma unroll
    for (int q = 0; q < 3; ++q) {
        int idx = t + q * 256;
        int r = idx >> 3;
        int kk = (idx & 7) << 2;
        wa[q] = *(const float4*)(wx + (size_t)r * DD + kbase + kk);
    }

    ull acc2[4][3] = {};

    for (int k0 = 0; k0 < 512; k0 += 32) {
        xs_t[xk + 0][xr0] = xa0.x;
        xs_t[xk + 1][xr0] = xa0.y;
        xs_t[xk + 2][xr0] = xa0.z;
        xs_t[xk + 3][xr0] = xa0.w;
        xs_t[xk + 0][xr1] = xa1.x;
        xs_t[xk + 1][xr1] = xa1.y;
        xs_t[xk + 2][xr1] = xa1.z;
        xs_t[xk + 3][xr1] = xa1.w;
        #pragma unroll
        for (int q = 0; q < 3; ++q) {
            int idx = t + q * 256;
            int r = idx >> 3;
            int kk = (idx & 7) << 2;
            ws[kk + 0][r] = wa[q].x;
            ws[kk + 1][r] = wa[q].y;
            ws[kk + 2][r] = wa[q].z;
            ws[kk + 3][r] = wa[q].w;
        }
        __syncthreads();

        if (k0 + 32 < 512) {
            xa0 = *(const float4*)(x + (size_t)(row0 + xr0) * DD + kbase + (k0 + 32) + xk);
            xa1 = *(const float4*)(x + (size_t)(row0 + xr1) * DD + kbase + (k0 + 32) + xk);
            #pragma unroll
            for (int q = 0; q < 3; ++q) {
                int idx = t + q * 256;
                int r = idx >> 3;
                int kk = (idx & 7) << 2;
                wa[q] = *(const float4*)(wx + (size_t)r * DD + kbase + (k0 + 32) + kk);
            }
        }

        #pragma unroll
        for (int kk = 0; kk < 32; ++kk) {
            ulonglong2 A0 = *(const ulonglong2*)&xs_t[kk][trow8];
            ulonglong2 A1 = *(const ulonglong2*)&xs_t[kk][trow8 + 4];
            float b0 = ws[kk][tcol];
            float b1 = ws[kk][tcol + 32];
            float b2 = ws[kk][tcol + 64];
            ull b0p = f2p(b0, b0);
            ull b1p = f2p(b1, b1);
            ull b2p = f2p(b2, b2);
            acc2[0][0] = fma2p(A0.x, b0p, acc2[0][0]);
            acc2[0][1] = fma2p(A0.x, b1p, acc2[0][1]);
            acc2[0][2] = fma2p(A0.x, b2p, acc2[0][2]);
            acc2[1][0] = fma2p(A0.y, b0p, acc2[1][0]);
            acc2[1][1] = fma2p(A0.y, b1p, acc2[1][1]);
            acc2[1][2] = fma2p(A0.y, b2p, acc2[1][2]);
            acc2[2][0] = fma2p(A1.x, b0p, acc2[2][0]);
            acc2[2][1] = fma2p(A1.x, b1p, acc2[2][1]);
            acc2[2][2] = fma2p(A1.x, b2p, acc2[2][2]);
            acc2[3][0] = fma2p(A1.y, b0p, acc2[3][0]);
            acc2[3][1] = fma2p(A1.y, b1p, acc2[3][1]);
            acc2[3][2] = fma2p(A1.y, b2p, acc2[3][2]);
        }
        __syncthreads();
    }

    float* dst = blockIdx.y ? g_xp1 : g_xp0;
    #pragma unroll
    for (int p = 0; p < 4; ++p) {
        #pragma unroll
        for (int j = 0; j < 3; ++j) {
            float lo, hi;
            p2f(acc2[p][j], lo, hi);
            dst[(size_t)(row0 + trow8 + 2 * p) * NE + tcol + 32 * j] = lo;
            dst[(size_t)(row0 + trow8 + 2 * p + 1) * NE + tcol + 32 * j] = hi;
        }
    }
}

// ---------------------------------------------------------------------------
// GEMM2: delta[row, d] = softplus( sum_r dr[row, r] * Wdt[d, r] + bias[d] )
// ---------------------------------------------------------------------------
__global__ void __launch_bounds__(256) k_gemm2(const float* __restrict__ wdt,
                                               const float* __restrict__ bias) {
    __shared__ float ds_t[64][66];   // [k][row]
    __shared__ float ws2[64][64];    // [k][col]
    const int t = threadIdx.x;
    const int row0 = blockIdx.y * 64;
    const int col0 = blockIdx.x * 64;

    #pragma unroll
    for (int q = 0; q < 4; ++q) {
        int idx = t + q * 256;
        int r = idx >> 4;
        int kk = (idx & 15) << 2;
        float4 v0 = *(const float4*)(g_xp0 + (size_t)(row0 + r) * NE + kk);
        float4 v1 = *(const float4*)(g_xp1 + (size_t)(row0 + r) * NE + kk);
        ds_t[kk + 0][r] = v0.x + v1.x;
        ds_t[kk + 1][r] = v0.y + v1.y;
        ds_t[kk + 2][r] = v0.z + v1.z;
        ds_t[kk + 3][r] = v0.w + v1.w;
    }
    #pragma unroll
    for (int q = 0; q < 4; ++q) {
        int idx = t + q * 256;
        int r = idx >> 4;
        int kk = (idx & 15) << 2;
        float4 v = *(const float4*)(wdt + (size_t)(col0 + r) * RK + kk);
        ws2[kk][r] = v.x; ws2[kk + 1][r] = v.y; ws2[kk + 2][r] = v.z; ws2[kk + 3][r] = v.w;
    }
    __syncthreads();

    const int trow8 = (t >> 5) * 8;
    const int tcol = t & 31;

    ull acc2[4][2] = {};
    #pragma unroll
    for (int kk = 0; kk < 64; ++kk) {
        float b0 = ws2[kk][tcol];
        float b1 = ws2[kk][tcol + 32];
        ull b0p = f2p(b0, b0);
        ull b1p = f2p(b1, b1);
        #pragma unroll
        for (int p = 0; p < 4; ++p) {
            ull a = *(const ull*)&ds_t[kk][trow8 + 2 * p];
            acc2[p][0] = fma2p(a, b0p, acc2[p][0]);
            acc2[p][1] = fma2p(a, b1p, acc2[p][1]);
        }
    }

    #pragma unroll
    for (int p = 0; p < 4; ++p) {
        #pragma unroll
        for (int j = 0; j < 2; ++j) {
            float lo, hi;
            p2f(acc2[p][j], lo, hi);
            int col = col0 + tcol + 32 * j;
            float bcol = bias[col];
            #pragma unroll
            for (int hh = 0; hh < 2; ++hh) {
                int row = row0 + trow8 + 2 * p + hh;
                float z = (hh == 0 ? lo : hi) + bcol;
                float az = fabsf(z);
                float e = ex2f_fast(-1.4426950408889634f * az);
                float l = lg2f_fast(1.0f + e) * 0.69314718055994531f;
                g_delta[(size_t)row * DD + col] = fmaxf(z, 0.0f) + l;
            }
        }
    }
}

// ---------------------------------------------------------------------------
// Scan pass 1: per (b, d, chunk) thread; B staged in smem; writes h_out + sdl.
// delta/x batch-loaded 8 steps at a time (MLP 16).
// ---------------------------------------------------------------------------
__global__ void __launch_bounds__(128) k_scan1(const float* __restrict__ x,
                                               const float* __restrict__ A_log) {
    __shared__ float s_b[LC][16];
    const int t = threadIdx.x;
    const int d = blockIdx.x * 128 + t;
    const int c = blockIdx.y;
    const int b = blockIdx.z;
    const int rbase = b * LL + c * LC;

    {
        int row = t >> 2;
        int c4 = (t & 3) << 2;
        float4 v0 = *(const float4*)(g_xp0 + (size_t)(rbase + row) * NE + RK + c4);
        float4 v1 = *(const float4*)(g_xp1 + (size_t)(rbase + row) * NE + RK + c4);
        float4 s; s.x = v0.x + v1.x; s.y = v0.y + v1.y; s.z = v0.z + v1.z; s.w = v0.w + v1.w;
        *(float4*)&s_b[row][c4] = s;
    }

    const float l2e = 1.4426950408889634f;
    float A2[NS];
    #pragma unroll
    for (int q = 0; q < 4; ++q) {
        float4 v = *(const float4*)(A_log + (size_t)d * NS + q * 4);
        A2[q * 4 + 0] = -__expf(v.x) * l2e;
        A2[q * 4 + 1] = -__expf(v.y) * l2e;
        A2[q * 4 + 2] = -__expf(v.z) * l2e;
        A2[q * 4 + 3] = -__expf(v.w) * l2e;
    }
    __syncthreads();

    ull h2[8] = {};
    float sdl = 0.0f;

    const float* dptr = g_delta + (size_t)rbase * DD + d;
    const float* xptr = x + (size_t)rbase * DD + d;

    #pragma unroll 1
    for (int s0 = 0; s0 < LC; s0 += 8) {
        float dlv[8], xvv[8];
        #pragma unroll
        for (int j = 0; j < 8; ++j) {
            dlv[j] = dptr[(size_t)(s0 + j) * DD];
            xvv[j] = xptr[(size_t)(s0 + j) * DD];
        }
        #pragma unroll
        for (int j = 0; j < 8; ++j) {
            const int s = s0 + j;
            const float dl = dlv[j];
            sdl += dl;
            const float dx = dl * xvv[j];
            const ull dxp = f2p(dx, dx);
            ulonglong2 Bq[4];
            #pragma unroll
            for (int u = 0; u < 4; ++u)
                Bq[u] = *(const ulonglong2*)&s_b[s][4 * u];
            #pragma unroll
            for (int q = 0; q < 8; ++q) {
                float e0 = ex2f_fast(dl * A2[2 * q]);
                float e1 = ex2f_fast(dl * A2[2 * q + 1]);
                ull a2 = f2p(e0, e1);
                ull Bv = (q & 1) ? Bq[q >> 1].y : Bq[q >> 1].x;
                h2[q] = fma2p(a2, h2[q], mul2p(dxp, Bv));
            }
        }
    }

    const size_t off = ((size_t)(b * NC + c) * DD + d) * NS;
    #pragma unroll
    for (int u = 0; u < 4; ++u) {
        ulonglong2 st;
        st.x = h2[2 * u]; st.y = h2[2 * u + 1];
        *(ulonglong2*)(g_ho + off + u * 4) = st;
    }
    g_sdl[(size_t)(b * NC + c) * DD + d] = sdl;
}

// ---------------------------------------------------------------------------
// Combine: per (b,d,n) thread over 64 chunks; ap recomputed from sdl on the fly.
// ---------------------------------------------------------------------------
__global__ void __launch_bounds__(128) k_comb(const float* __restrict__ A_log) {
    const int gid = blockIdx.x * 128 + threadIdx.x;     // 0 .. BB*DDNS-1
    const int b = gid >> 14;            // DDNS = 16384
    const int rem = gid & (DDNS - 1);   // d*NS + n
    const int d = rem >> 4;
    const int n = rem & 15;

    const float A2 = -__expf(A_log[(size_t)d * NS + n]) * 1.4426950408889634f;

    float h = 0.0f;
    #pragma unroll
    for (int c0 = 0; c0 < NC; c0 += 16) {
        float sv[16], hv[16];
        #pragma unroll
        for (int j = 0; j < 16; ++j) {
            const int c = c0 + j;
            sv[j] = g_sdl[(size_t)(b * NC + c) * DD + d];
            hv[j] = g_ho[(size_t)(b * NC + c) * DDNS + rem];
        }
        #pragma unroll
        for (int j = 0; j < 16; ++j) {
            const size_t off = (size_t)(b * NC + c0 + j) * DDNS + rem;
            g_hi[off] = h;
            h = fmaf(ex2f_fast(A2 * sv[j]), h, hv[j]);
        }
    }
}

// ---------------------------------------------------------------------------
// Scan pass 2: replay with h_in; B and C staged in smem; y output.
// delta/x batch-loaded 8 steps at a time (MLP 16).
// ---------------------------------------------------------------------------
__global__ void __launch_bounds__(128) k_scan2(const float* __restrict__ x,
                                               const float* __restrict__ A_log,
                                               const float* __restrict__ Dw,
                                               float* __restrict__ out) {
    __shared__ float s_bc[LC][32];   // [step][0..15 = B, 16..31 = C]
    const int t = threadIdx.x;
    const int d = blockIdx.x * 128 + t;
    const int c = blockIdx.y;
    const int b = blockIdx.z;
    const int rbase = b * LL + c * LC;

    {
        int row = t >> 2;
        int c4 = (t & 3) << 2;
        float4 v0 = *(const float4*)(g_xp0 + (size_t)(rbase + row) * NE + RK + c4);
        float4 v1 = *(const float4*)(g_xp1 + (size_t)(rbase + row) * NE + RK + c4);
        float4 s0; s0.x = v0.x + v1.x; s0.y = v0.y + v1.y; s0.z = v0.z + v1.z; s0.w = v0.w + v1.w;
        *(float4*)&s_bc[row][c4] = s0;
        float4 w0 = *(const float4*)(g_xp0 + (size_t)(rbase + row) * NE + RK + NS + c4);
        float4 w1 = *(const float4*)(g_xp1 + (size_t)(rbase + row) * NE + RK + NS + c4);
        float4 s1; s1.x = w0.x + w1.x; s1.y = w0.y + w1.y; s1.z = w0.z + w1.z; s1.w = w0.w + w1.w;
        *(float4*)&s_bc[row][16 + c4] = s1;
    }

    const float l2e = 1.4426950408889634f;
    float A2[NS];
    #pragma unroll
    for (int q = 0; q < 4; ++q) {
        float4 v = *(const float4*)(A_log + (size_t)d * NS + q * 4);
        A2[q * 4 + 0] = -__expf(v.x) * l2e;
        A2[q * 4 + 1] = -__expf(v.y) * l2e;
        A2[q * 4 + 2] = -__expf(v.z) * l2e;
        A2[q * 4 + 3] = -__expf(v.w) * l2e;
    }
    const float Dv = Dw[d];

    ull h2[8];
    {
        const size_t off = ((size_t)(b * NC + c) * DD + d) * NS;
        #pragma unroll
        for (int u = 0; u < 4; ++u) {
            ulonglong2 v = *(const ulonglong2*)(g_hi + off + u * 4);
            h2[2 * u] = v.x;
            h2[2 * u + 1] = v.y;
        }
    }
    __syncthreads();

    const float* dptr = g_delta + (size_t)rbase * DD + d;
    const float* xptr = x + (size_t)rbase * DD + d;

    #pragma unroll 1
    for (int s0 = 0; s0 < LC; s0 += 8) {
        float dlv[8], xvv[8];
        #pragma unroll
        for (int j = 0; j < 8; ++j) {
            dlv[j] = dptr[(size_t)(s0 + j) * DD];
            xvv[j] = xptr[(size_t)(s0 + j) * DD];
        }
        #pragma unroll
        for (int j = 0; j < 8; ++j) {
            const int s = s0 + j;
            const float dl = dlv[j];
            const float xv = xvv[j];
            const float dx = dl * xv;
            const ull dxp = f2p(dx, dx);
            ulonglong2 Bq[4], Cq[4];
            #pragma unroll
            for (int u = 0; u < 4; ++u) {
                Bq[u] = *(const ulonglong2*)&s_bc[s][4 * u];
                Cq[u] = *(const ulonglong2*)&s_bc[s][16 + 4 * u];
            }

            ull y2 = 0;
            #pragma unroll
            for (int q = 0; q < 8; ++q) {
                float e0 = ex2f_fast(dl * A2[2 * q]);
                float e1 = ex2f_fast(dl * A2[2 * q + 1]);
                ull a2 = f2p(e0, e1);
                ull Bv = (q & 1) ? Bq[q >> 1].y : Bq[q >> 1].x;
                ull Cv = (q & 1) ? Cq[q >> 1].y : Cq[q >> 1].x;
                h2[q] = fma2p(a2, h2[q], mul2p(dxp, Bv));
                y2 = fma2p(h2[q], Cv, y2);
            }
            float ylo, yhi;
            p2f(y2, ylo, yhi);
            out[(size_t)(rbase + s) * DD + d] = fmaf(xv, Dv, ylo + yhi);
        }
    }
}

// ---------------------------------------------------------------------------
extern "C" void kernel_launch(void* const* d_in, const int* in_sizes, int n_in,
                              void* d_out, int out_size) {
    const float* x     = (const float*)d_in[0];
    const float* A_log = (const float*)d_in[1];
    const float* Dw    = (const float*)d_in[2];
    const float* wx    = (const float*)d_in[3];
    const float* wdt   = (const float*)d_in[4];
    const float* bias  = (const float*)d_in[5];
    float* out = (float*)d_out;

    dim3 g1(NROW / 64, 2);
    k_gemm1<<<g1, 256>>>(x, wx);

    dim3 g2(DD / 64, NROW / 64);
    k_gemm2<<<g2, 256>>>(wdt, bias);

    dim3 gs(DD / 128, NC, BB);
    k_scan1<<<gs, 128>>>(x, A_log);

    k_comb<<<(BB * DDNS) / 128, 128>>>(A_log);

    k_scan2<<<gs, 128>>>(x, A_log, Dw, out);
}